// round 1
// baseline (speedup 1.0000x reference)
#include <cuda_runtime.h>
#include <math.h>

#define B    64
#define C    768
#define HW   576
#define NM   50
#define NSEL (B*NM)   // 3200
#define EPSV 1e-5f

// ---------------- scratch (static device memory; no allocations) ----------------
__device__ float  g_G[(size_t)B*HW*HW];        // 84.9 MB Gram for cdist
__device__ float  g_a2[B*HW], g_b2[B*HW];      // squared norms
__device__ float  g_d2[2][B*HW];               // min d2 per input point
__device__ int    g_nn[2][B*HW];               // argmin index
__device__ int    g_sel_in[2][NSEL];           // selected input row idx
__device__ int    g_sel_c [2][NSEL];           // matched candidate row idx
__device__ float  g_X[4][(size_t)NSEL*C];      // gathered maps (n,c) row-major
__device__ float  g_S[6][(size_t)C*C];         // Grams X^T X (upper tiles valid)
__device__ float  g_csp[6][16][C];             // colsum partials
__device__ float  g_colsum[6][C];
__device__ double g_acc[32];

// ---------------- helpers ----------------
__device__ __forceinline__ float blockReduceSum(float v) {
    __shared__ float sw[32];
    int lane = threadIdx.x & 31, w = threadIdx.x >> 5;
    #pragma unroll
    for (int o = 16; o; o >>= 1) v += __shfl_xor_sync(~0u, v, o);
    if (lane == 0) sw[w] = v;
    __syncthreads();
    int nw = (blockDim.x + 31) >> 5;
    v = (threadIdx.x < nw) ? sw[threadIdx.x] : 0.f;
    if (w == 0) {
        #pragma unroll
        for (int o = 16; o; o >>= 1) v += __shfl_xor_sync(~0u, v, o);
    }
    return v; // valid in thread 0
}

// ---------------- kernels ----------------
__global__ void k_init() { if (threadIdx.x < 32) g_acc[threadIdx.x] = 0.0; }

// squared norms of map rows: maps[b,p,:] = spatial[b,:,p]
__global__ void k_norms(const float* __restrict__ s1, const float* __restrict__ s2) {
    int b = blockIdx.x, p = threadIdx.x;
    const float* src = blockIdx.y ? s2 : s1;
    float*       dst = blockIdx.y ? g_b2 : g_a2;
    const float* base = src + (size_t)b * C * HW + p;
    float s = 0.f;
    #pragma unroll 8
    for (int c = 0; c < C; c++) { float v = base[(size_t)c * HW]; s += v * v; }
    dst[b * HW + p] = s;
}

// G[b][m][n] = sum_c S1[b][c][m] * S2[b][c][n]   (both operands K-major -> coalesced)
__global__ void __launch_bounds__(256) k_gemm(const float* __restrict__ s1,
                                              const float* __restrict__ s2) {
    int b  = blockIdx.z;
    int m0 = blockIdx.y * 64, n0 = blockIdx.x * 64;
    const float* A  = s1 + (size_t)b * C * HW;
    const float* Bp = s2 + (size_t)b * C * HW;
    __shared__ float As[16][64], Bs[16][64];
    int tid = threadIdx.x;
    int tx = tid & 15, ty = tid >> 4;
    int lk = tid >> 4, lo = (tid & 15) * 4;
    float acc[4][4] = {};
    for (int k0 = 0; k0 < C; k0 += 16) {
        *(float4*)&As[lk][lo] = *(const float4*)&A [(size_t)(k0 + lk) * HW + m0 + lo];
        *(float4*)&Bs[lk][lo] = *(const float4*)&Bp[(size_t)(k0 + lk) * HW + n0 + lo];
        __syncthreads();
        #pragma unroll
        for (int kk = 0; kk < 16; kk++) {
            float a[4], bb[4];
            *(float4*)a  = *(float4*)&As[kk][ty * 4];
            *(float4*)bb = *(float4*)&Bs[kk][tx * 4];
            #pragma unroll
            for (int i = 0; i < 4; i++)
                #pragma unroll
                for (int j = 0; j < 4; j++) acc[i][j] += a[i] * bb[j];
        }
        __syncthreads();
    }
    float* Gout = g_G + (size_t)b * HW * HW;
    #pragma unroll
    for (int i = 0; i < 4; i++) {
        int m = m0 + ty * 4 + i;
        *(float4*)&Gout[(size_t)m * HW + n0 + tx * 4] = *(float4*)acc[i];
    }
}

// dir 1: per row m, argmin_n (a2+b2-2G) == argmin_n (b2[n]-2G[m,n]); warp per row
__global__ void k_rowmin() {
    int gwarp = (blockIdx.x * blockDim.x + threadIdx.x) >> 5;
    int lane  = threadIdx.x & 31;
    int b = gwarp / HW, m = gwarp % HW;
    const float* Grow = g_G + ((size_t)b * HW + m) * HW;
    const float* b2   = g_b2 + b * HW;
    float best = INFINITY; int bi = 0;
    for (int n = lane; n < HW; n += 32) {
        float v = b2[n] - 2.f * Grow[n];
        if (v < best || (v == best && n < bi)) { best = v; bi = n; }
    }
    #pragma unroll
    for (int o = 16; o; o >>= 1) {
        float ov = __shfl_xor_sync(~0u, best, o);
        int   oi = __shfl_xor_sync(~0u, bi, o);
        if (ov < best || (ov == best && oi < bi)) { best = ov; bi = oi; }
    }
    if (lane == 0) {
        float d2 = g_a2[b * HW + m] + best;
        g_d2[0][b * HW + m] = d2 > 0.f ? d2 : 0.f;
        g_nn[0][b * HW + m] = bi;
    }
}

// dir 2: per column n, argmin_m (a2[m]-2G[m,n]); thread per column (coalesced)
__global__ void k_colmin() {
    int b = blockIdx.x, n = threadIdx.x;
    const float* Gb = g_G + (size_t)b * HW * HW;
    const float* a2 = g_a2 + b * HW;
    float best = INFINITY; int bi = 0;
    #pragma unroll 4
    for (int m = 0; m < HW; m++) {
        float v = a2[m] - 2.f * Gb[(size_t)m * HW + n];
        if (v < best) { best = v; bi = m; }   // strict < -> lowest index on ties
    }
    float d2 = g_b2[b * HW + n] + best;
    g_d2[1][b * HW + n] = d2 > 0.f ? d2 : 0.f;
    g_nn[1][b * HW + n] = bi;
}

// rank-based top-50 smallest (ties -> lowest index), matches jax top_k semantics
__global__ void k_select() {
    int b = blockIdx.x, dir = blockIdx.y;
    __shared__ float sd[HW];
    int i = threadIdx.x;
    sd[i] = g_d2[dir][b * HW + i];
    __syncthreads();
    float di = sd[i];
    int rank = 0;
    for (int j = 0; j < HW; j++) {
        float dj = sd[j];
        rank += (dj < di) || (dj == di && j < i);
    }
    if (rank < NM) {
        g_sel_in[dir][b * NM + rank] = i;
        g_sel_c [dir][b * NM + rank] = g_nn[dir][b * HW + i];
    }
}

// gather selected rows into (n,c) row-major scratch + accumulate invariance sums
__global__ void k_gather(const float* __restrict__ s1, const float* __restrict__ s2) {
    int k = blockIdx.x, b = blockIdx.y, dir = blockIdx.z;
    const float* srcin = dir ? s2 : s1;
    const float* srcc  = dir ? s1 : s2;
    int pin = g_sel_in[dir][b * NM + k];
    int pc  = g_sel_c [dir][b * NM + k];
    float* Xin = g_X[dir * 2 + 0];
    float* Xc  = g_X[dir * 2 + 1];
    int row = b * NM + k;
    float lsum = 0.f;
    for (int c = threadIdx.x; c < C; c += 256) {
        float vi = srcin[((size_t)b * C + c) * HW + pin];
        float vc = srcc [((size_t)b * C + c) * HW + pc];
        Xin[(size_t)row * C + c] = vi;
        Xc [(size_t)row * C + c] = vc;
        float d = vi - vc; lsum += d * d;
    }
    float tot = blockReduceSum(lsum);
    if (threadIdx.x == 0) atomicAdd(&g_acc[1 + dir], (double)tot);
}

__global__ void k_pooled_inv(const float* __restrict__ p1, const float* __restrict__ p2) {
    float lsum = 0.f;
    for (int i = blockIdx.x * blockDim.x + threadIdx.x; i < B * C; i += gridDim.x * blockDim.x) {
        float d = p1[i] - p2[i]; lsum += d * d;
    }
    float tot = blockReduceSum(lsum);
    if (threadIdx.x == 0) atomicAdd(&g_acc[0], (double)tot);
}

__device__ __forceinline__ const float* tensor_ptr(int t, const float* p1, const float* p2) {
    if (t < 4) return g_X[t];
    return (t == 4) ? p1 : p2;
}
__device__ __forceinline__ int tensor_n(int t) { return (t < 4) ? NSEL : B; }

// column sums (partials, deterministic 2-stage)
__global__ void k_colsum_part(const float* __restrict__ p1, const float* __restrict__ p2) {
    int t = blockIdx.x, chunk = blockIdx.y, c = threadIdx.x;
    const float* X = tensor_ptr(t, p1, p2);
    int n = tensor_n(t);
    int step = n / 16;
    int n0 = chunk * step, n1 = n0 + step;
    float s = 0.f;
    for (int i = n0; i < n1; i++) s += X[(size_t)i * C + c];
    g_csp[t][chunk][c] = s;
}
__global__ void k_colsum_fin() {
    int t = blockIdx.x, c = threadIdx.x;
    float s = 0.f;
    #pragma unroll
    for (int k = 0; k < 16; k++) s += g_csp[t][k][c];
    g_colsum[t][c] = s;
}

// S = X^T X, upper-triangle 64x64 tiles only (78 tiles of 12x12)
__global__ void __launch_bounds__(256) k_gram(const float* __restrict__ p1,
                                              const float* __restrict__ p2) {
    int t = blockIdx.y;
    const float* X = tensor_ptr(t, p1, p2);
    int n = tensor_n(t);
    // linear tile -> (i,j), i<=j among 12x12
    int idx = blockIdx.x, ti = 0;
    while (idx >= 12 - ti) { idx -= 12 - ti; ti++; }
    int tj = ti + idx;
    int i0 = ti * 64, j0 = tj * 64;

    __shared__ float As[16][64], Bs[16][64];
    int tid = threadIdx.x;
    int tx = tid & 15, ty = tid >> 4;
    int lk = tid >> 4, lo = (tid & 15) * 4;
    float acc[4][4] = {};
    for (int k0 = 0; k0 < n; k0 += 16) {
        *(float4*)&As[lk][lo] = *(const float4*)&X[(size_t)(k0 + lk) * C + i0 + lo];
        *(float4*)&Bs[lk][lo] = *(const float4*)&X[(size_t)(k0 + lk) * C + j0 + lo];
        __syncthreads();
        #pragma unroll
        for (int kk = 0; kk < 16; kk++) {
            float a[4], bb[4];
            *(float4*)a  = *(float4*)&As[kk][ty * 4];
            *(float4*)bb = *(float4*)&Bs[kk][tx * 4];
            #pragma unroll
            for (int i = 0; i < 4; i++)
                #pragma unroll
                for (int j = 0; j < 4; j++) acc[i][j] += a[i] * bb[j];
        }
        __syncthreads();
    }
    float* Sp = g_S[t];
    #pragma unroll
    for (int i = 0; i < 4; i++) {
        int c1 = i0 + ty * 4 + i;
        *(float4*)&Sp[(size_t)c1 * C + j0 + tx * 4] = *(float4*)acc[i];
    }
}

// std term per tensor: sum_c relu(1 - sqrt(var_c + eps)), var from Gram diag + colsum
__global__ void k_std() {
    int t = blockIdx.x, c = threadIdx.x;
    float n  = (float)tensor_n(t);
    float mu = g_colsum[t][c] / n;
    float Scc = g_S[t][(size_t)c * C + c];
    float var = (Scc - n * mu * mu) / (n - 1.f);
    float sd  = sqrtf(var + EPSV);
    float contrib = fmaxf(1.f - sd, 0.f);
    float tot = blockReduceSum(contrib);
    if (threadIdx.x == 0) atomicAdd(&g_acc[3 + t], (double)tot);
}

// off-diagonal squared sum of cov = (S - n mu mu^T)/(n-1), upper tiles, x2 weight
__global__ void k_cov() {
    int t = blockIdx.y;
    float n = (float)tensor_n(t);
    float inv_nm1 = 1.f / (n - 1.f);
    int idx = blockIdx.x, ti = 0;
    while (idx >= 12 - ti) { idx -= 12 - ti; ti++; }
    int tj = ti + idx;
    int i0 = ti * 64, j0 = tj * 64;
    const float* Sp = g_S[t];
    float lsum = 0.f;
    #pragma unroll
    for (int it = 0; it < 16; it++) {
        int e = it * 256 + threadIdx.x;
        int r = e >> 6, cc = e & 63;
        int c1 = i0 + r, c2 = j0 + cc;
        if (c2 > c1) {
            float mu1 = g_colsum[t][c1] / n;
            float mu2 = g_colsum[t][c2] / n;
            float cov = (Sp[(size_t)c1 * C + c2] - n * mu1 * mu2) * inv_nm1;
            lsum += 2.f * cov * cov;
        }
    }
    float tot = blockReduceSum(lsum);
    if (threadIdx.x == 0) atomicAdd(&g_acc[10 + t], (double)tot);
}

__global__ void k_final(float* __restrict__ out) {
    double inv_g = g_acc[0] / (double)(B * C);
    double inv1  = g_acc[1] / (double)((size_t)NSEL * C);
    double inv2  = g_acc[2] / (double)((size_t)NSEL * C);
    double stdt[6], covt[6];
    for (int t = 0; t < 6; t++) {
        stdt[t] = (g_acc[3 + t] / (double)C) * 0.5;   // mean(relu)/2
        covt[t] = g_acc[10 + t] / (double)C;          // off_diag_sq_sum / C
    }
    double glob = 25.0 * inv_g + 25.0 * (stdt[4] + stdt[5]) + (covt[4] + covt[5]);
    double loc  = 0.5 * (25.0 * inv1 + 25.0 * inv2)
                + 0.5 * (25.0 * (stdt[0] + stdt[1]) + 25.0 * (stdt[2] + stdt[3]))
                + 0.5 * ((covt[0] + covt[1]) + (covt[2] + covt[3]));
    out[0] = (float)(0.5 * glob + 0.5 * loc);
}

// ---------------- launch ----------------
extern "C" void kernel_launch(void* const* d_in, const int* in_sizes, int n_in,
                              void* d_out, int out_size) {
    const float* s1 = (const float*)d_in[0];
    const float* p1 = (const float*)d_in[1];
    const float* s2 = (const float*)d_in[2];
    const float* p2 = (const float*)d_in[3];
    float* out = (float*)d_out;

    k_init<<<1, 32>>>();
    k_norms<<<dim3(B, 2), HW>>>(s1, s2);
    k_gemm<<<dim3(9, 9, B), 256>>>(s1, s2);
    k_rowmin<<<(B * HW) / 8, 256>>>();
    k_colmin<<<B, HW>>>();
    k_select<<<dim3(B, 2), HW>>>();
    k_gather<<<dim3(NM, B, 2), 256>>>(s1, s2);
    k_pooled_inv<<<48, 256>>>(p1, p2);
    k_colsum_part<<<dim3(6, 16), C>>>(p1, p2);
    k_colsum_fin<<<6, C>>>();
    k_gram<<<dim3(78, 6), 256>>>(p1, p2);
    k_std<<<6, C>>>();
    k_cov<<<dim3(78, 6), 256>>>();
    k_final<<<1, 1>>>(out);
}